// round 6
// baseline (speedup 1.0000x reference)
#include <cuda_runtime.h>
#include <cstdint>
#include <math.h>

#define BATCH 2
#define DM_   256
#define LEN_  18720
#define ROWS_ (BATCH * LEN_)   // 37440
#define NOFF  384              // M*LV*P*3
#define NATT  128              // M*LV*P
#define DFF_  1024

// ---------------- scratch (static device globals; no allocs) ----------------
__device__ float g_src [(size_t)ROWS_ * DM_];
__device__ float g_pos [(size_t)ROWS_ * DM_];
__device__ float g_val [(size_t)ROWS_ * DM_];
__device__ float g_agg [(size_t)ROWS_ * DM_];
__device__ float g_off [(size_t)ROWS_ * NOFF];
__device__ float g_attn[(size_t)ROWS_ * NATT];
__device__ float g_ff  [(size_t)ROWS_ * DFF_];

// ---------------- helpers ----------------------------------------------------
__device__ __forceinline__ float to_tf32(float x) {
    uint32_t u;
    asm("cvt.rna.tf32.f32 %0, %1;" : "=r"(u) : "f"(x));
    return __uint_as_float(u);
}

__device__ __forceinline__ void mma_tf32(float* c, const uint32_t* a, const uint32_t* b) {
    asm volatile(
        "mma.sync.aligned.m16n8k8.row.col.f32.tf32.tf32.f32 "
        "{%0,%1,%2,%3},{%4,%5,%6,%7},{%8,%9},{%0,%1,%2,%3};"
        : "+f"(c[0]), "+f"(c[1]), "+f"(c[2]), "+f"(c[3])
        : "r"(a[0]), "r"(a[1]), "r"(a[2]), "r"(a[3]), "r"(b[0]), "r"(b[1]));
}

// ---------------- flatten + transpose: [B,DM,S] -> rows [b, base+s, c] -------
__global__ void flatten_kernel(const float* __restrict__ in, float* __restrict__ out,
                               const float* __restrict__ lvl_emb, int S, int base)
{
    __shared__ float tile[32][33];
    const int b  = blockIdx.z;
    const int s0 = blockIdx.x * 32;
    const int c0 = blockIdx.y * 32;
    const int tx = threadIdx.x, ty = threadIdx.y; // 32 x 8

    #pragma unroll
    for (int i = 0; i < 32; i += 8) {
        int c = c0 + ty + i, s = s0 + tx;
        float v = 0.f;
        if (s < S) v = in[((size_t)b * DM_ + c) * S + s];
        tile[ty + i][tx] = v;
    }
    __syncthreads();
    float emb = lvl_emb ? lvl_emb[c0 + tx] : 0.f;
    #pragma unroll
    for (int i = 0; i < 32; i += 8) {
        int s = s0 + ty + i, c = c0 + tx;
        if (s < S)
            out[((size_t)b * LEN_ + base + s) * DM_ + c] = tile[tx][ty + i] + emb;
    }
}

// ---------------- TF32 tensor-core GEMM, pipelined + fragment-layout smem ----
// C[M,N] = (A (+A2)) @ W + bias, optional relu. Block 128x128, BK=16,
// 256 threads = 8 warps, warp tile 64x32 via m16n8k8 tf32 mma.
// Smem holds slabs in fragment-native order: per-thread A regs are one float4,
// B regs one float2 -> 16 vector LDS per slab (was 48 scalar LDS).
__global__ __launch_bounds__(256) void tgemm_kernel(
    const float* __restrict__ A, const float* __restrict__ A2,
    const float* __restrict__ W, const float* __restrict__ bias,
    float* __restrict__ C, int Mrows, int N, int K, int relu)
{
    // A slab: 128 rows x 16 k. u = mt*2 + kh (mt: 16-row tile, kh: 8-wide k half)
    // lane = g*4 + t4 holds regs {(g,t4),(g+8,t4),(g,t4+4),(g+8,t4+4)}
    __shared__ float AsF[2][16][32][4];
    // B slab: 16 k x 128 n. [kh][nt (8-col tile)][lane]{(t4,g),(t4+4,g)}
    __shared__ float BsF[2][2][16][32][2];

    const int bm = blockIdx.y * 128;
    const int bn = blockIdx.x * 128;
    const int tid  = threadIdx.x;
    const int wid  = tid >> 5;
    const int lane = tid & 31;
    const int wm   = (wid & 1) * 64;   // warp row base in tile
    const int wn   = (wid >> 1) * 32;  // warp col base in tile
    const int mt0  = wm >> 4;          // first m-tile index for this warp
    const int nt0  = wn >> 3;          // first n-tile index

    float acc[4][4][4];
    #pragma unroll
    for (int i = 0; i < 4; i++)
        #pragma unroll
        for (int j = 0; j < 4; j++)
            #pragma unroll
            for (int r = 0; r < 4; r++) acc[i][j][r] = 0.f;

    float4 pa[2], pb[2];

    auto load_slab = [&](int k0) {
        #pragma unroll
        for (int t = 0; t < 2; t++) {
            int v   = tid + t * 256;
            int row = v >> 2;
            int c4  = (v & 3) * 4;
            int grow = bm + row;
            float4 av = make_float4(0.f, 0.f, 0.f, 0.f);
            if (grow < Mrows) {
                size_t gi = (size_t)grow * K + k0 + c4;
                av = *(const float4*)(A + gi);
                if (A2) {
                    float4 a2 = *(const float4*)(A2 + gi);
                    av.x += a2.x; av.y += a2.y; av.z += a2.z; av.w += a2.w;
                }
            }
            pa[t] = av;
        }
        #pragma unroll
        for (int t = 0; t < 2; t++) {
            int v  = tid + t * 256;
            int kr = v >> 5;
            int c4 = (v & 31) * 4;
            pb[t] = *(const float4*)(W + (size_t)(k0 + kr) * N + bn + c4);
        }
    };

    auto store_slab = [&](int buf) {
        #pragma unroll
        for (int t = 0; t < 2; t++) {
            int v   = tid + t * 256;
            int m   = v >> 2;            // 0..127
            int c4  = (v & 3) * 4;       // k base: 0,4,8,12
            int mt  = m >> 4;
            int r   = m & 15;
            int gg  = r & 7;
            int him = r >> 3;
            int kh  = c4 >> 3;           // 0 or 1
            int hik = (c4 & 7) >> 2;     // 0 or 1
            int u   = mt * 2 + kh;
            int reg = him + 2 * hik;
            float vv[4] = {pa[t].x, pa[t].y, pa[t].z, pa[t].w};
            #pragma unroll
            for (int i = 0; i < 4; i++)
                AsF[buf][u][gg * 4 + i][reg] = to_tf32(vv[i]);
        }
        #pragma unroll
        for (int t = 0; t < 2; t++) {
            int v   = tid + t * 256;
            int kr  = v >> 5;            // k row 0..15
            int c4  = (v & 31) * 4;      // n base
            int kh  = kr >> 3;
            int c   = kr & 7;
            int tt  = c & 3;
            int hik = c >> 2;
            int nt  = c4 >> 3;
            int g0  = c4 & 7;            // 0 or 4
            float vv[4] = {pb[t].x, pb[t].y, pb[t].z, pb[t].w};
            #pragma unroll
            for (int i = 0; i < 4; i++)
                BsF[buf][kh][nt][(g0 + i) * 4 + tt][hik] = to_tf32(vv[i]);
        }
    };

    auto compute_slab = [&](int buf) {
        #pragma unroll
        for (int kh = 0; kh < 2; kh++) {
            float4 afv[4];
            #pragma unroll
            for (int mf = 0; mf < 4; mf++)
                afv[mf] = *(const float4*)&AsF[buf][(mt0 + mf) * 2 + kh][lane][0];
            float2 bfv[4];
            #pragma unroll
            for (int nf = 0; nf < 4; nf++)
                bfv[nf] = *(const float2*)&BsF[buf][kh][nt0 + nf][lane][0];
            #pragma unroll
            for (int mf = 0; mf < 4; mf++)
                #pragma unroll
                for (int nf = 0; nf < 4; nf++)
                    mma_tf32(acc[mf][nf], (const uint32_t*)&afv[mf], (const uint32_t*)&bfv[nf]);
        }
    };

    const int nslab = K >> 4;
    load_slab(0);
    store_slab(0);
    __syncthreads();

    for (int s = 0; s < nslab; s++) {
        int buf = s & 1;
        if (s + 1 < nslab) load_slab((s + 1) << 4);   // LDGs in flight during MMAs
        compute_slab(buf);
        if (s + 1 < nslab) store_slab(buf ^ 1);
        __syncthreads();
    }

    // ---- epilogue: bias (+relu), guarded stores ----
    const int g  = lane >> 2;
    const int t4 = lane & 3;
    #pragma unroll
    for (int mf = 0; mf < 4; mf++) {
        int row0 = bm + wm + mf * 16 + g;
        int row1 = row0 + 8;
        #pragma unroll
        for (int nf = 0; nf < 4; nf++) {
            int col = bn + wn + nf * 8 + 2 * t4;
            float b0 = bias[col], b1 = bias[col + 1];
            float v0 = acc[mf][nf][0] + b0;
            float v1 = acc[mf][nf][1] + b1;
            float v2 = acc[mf][nf][2] + b0;
            float v3 = acc[mf][nf][3] + b1;
            if (relu) {
                v0 = fmaxf(v0, 0.f); v1 = fmaxf(v1, 0.f);
                v2 = fmaxf(v2, 0.f); v3 = fmaxf(v3, 0.f);
            }
            if (row0 < Mrows) *(float2*)(C + (size_t)row0 * N + col) = make_float2(v0, v1);
            if (row1 < Mrows) *(float2*)(C + (size_t)row1 * N + col) = make_float2(v2, v3);
        }
    }
}

// ---------------- softmax over 16 (per b,n,m) --------------------------------
__global__ void softmax_kernel(float* __restrict__ attn, int total)
{
    int i = blockIdx.x * blockDim.x + threadIdx.x;
    if (i >= total) return;
    float* p = attn + (size_t)i * 16;
    float v[16];
    #pragma unroll
    for (int t = 0; t < 4; t++) {
        float4 f = *(float4*)(p + t * 4);
        v[t*4+0] = f.x; v[t*4+1] = f.y; v[t*4+2] = f.z; v[t*4+3] = f.w;
    }
    float mx = v[0];
    #pragma unroll
    for (int t = 1; t < 16; t++) mx = fmaxf(mx, v[t]);
    float s = 0.f;
    #pragma unroll
    for (int t = 0; t < 16; t++) { v[t] = expf(v[t] - mx); s += v[t]; }
    float inv = 1.f / s;
    #pragma unroll
    for (int t = 0; t < 4; t++) {
        float4 f = make_float4(v[t*4+0]*inv, v[t*4+1]*inv, v[t*4+2]*inv, v[t*4+3]*inv);
        *(float4*)(p + t * 4) = f;
    }
}

// ---------------- deformable trilinear sampling ------------------------------
__global__ __launch_bounds__(256) void sample_kernel(
    const float* __restrict__ value, const float* __restrict__ off,
    const float* __restrict__ attn, float* __restrict__ agg)
{
    const int bn = blockIdx.x;
    const int b  = bn / LEN_;
    const int n  = bn - b * LEN_;
    const int tid = threadIdx.x;
    const int m  = tid >> 5, dh = tid & 31;

    float rc0, rc1, rc2;
    {
        int s, z, r, y, x;
        if (n < 16384)      { s = n;         z = s >> 10; r = s & 1023; y = r >> 5; x = r & 31;
            rc0 = (z + .5f) * (1.f/16.f); rc1 = (y + .5f) * (1.f/32.f); rc2 = (x + .5f) * (1.f/32.f); }
        else if (n < 18432) { s = n - 16384; z = s >> 8;  r = s & 255;  y = r >> 4; x = r & 15;
            rc0 = (z + .5f) * (1.f/8.f);  rc1 = (y + .5f) * (1.f/16.f); rc2 = (x + .5f) * (1.f/16.f); }
        else if (n < 18688) { s = n - 18432; z = s >> 6;  r = s & 63;   y = r >> 3; x = r & 7;
            rc0 = (z + .5f) * (1.f/4.f);  rc1 = (y + .5f) * (1.f/8.f);  rc2 = (x + .5f) * (1.f/8.f); }
        else                { s = n - 18688; z = s >> 4;  r = s & 15;   y = r >> 2; x = r & 3;
            rc0 = (z + .5f) * .5f;        rc1 = (y + .5f) * .25f;       rc2 = (x + .5f) * .25f; }
    }

    const float* offp = off  + ((size_t)bn * 8 + m) * 48;
    const float* attp = attn + ((size_t)bn * 8 + m) * 16;

    const int LD[4] = {16, 8, 4, 2};
    const int LH[4] = {32, 16, 8, 4};
    const int LW[4] = {32, 16, 8, 4};
    const int LB[4] = {0, 16384, 18432, 18688};

    float acc = 0.f;
    #pragma unroll
    for (int lvl = 0; lvl < 4; lvl++) {
        const int D = LD[lvl], H = LH[lvl], Wd = LW[lvl];
        const float* vptr = value + ((size_t)b * LEN_ + LB[lvl]) * DM_ + m * 32 + dh;
        #pragma unroll
        for (int p = 0; p < 4; p++) {
            float o0 = __ldg(offp + lvl * 12 + p * 3 + 0);
            float o1 = __ldg(offp + lvl * 12 + p * 3 + 1);
            float o2 = __ldg(offp + lvl * 12 + p * 3 + 2);
            float a  = __ldg(attp + lvl * 4 + p);
            float x = fmaf(rc0, (float)Wd, o0) - 0.5f;
            float y = fmaf(rc1, (float)H,  o1) - 0.5f;
            float z = fmaf(rc2, (float)D,  o2) - 0.5f;
            float xf = floorf(x), yf = floorf(y), zf = floorf(z);
            float fx = x - xf, fy = y - yf, fz = z - zf;
            int x0 = (int)xf, y0 = (int)yf, z0 = (int)zf;
            float wx0 = (1.f - fx) * a, wx1 = fx * a;
            float wy0 = 1.f - fy,       wy1 = fy;
            float wz0 = 1.f - fz,       wz1 = fz;
            #pragma unroll
            for (int dz = 0; dz < 2; dz++) {
                int zi = z0 + dz;
                if ((unsigned)zi >= (unsigned)D) continue;
                float wz_ = dz ? wz1 : wz0;
                #pragma unroll
                for (int dy = 0; dy < 2; dy++) {
                    int yi = y0 + dy;
                    if ((unsigned)yi >= (unsigned)H) continue;
                    float wzy = wz_ * (dy ? wy1 : wy0);
                    #pragma unroll
                    for (int dx = 0; dx < 2; dx++) {
                        int xi = x0 + dx;
                        if ((unsigned)xi >= (unsigned)Wd) continue;
                        float w = wzy * (dx ? wx1 : wx0);
                        int idx = (zi * H + yi) * Wd + xi;
                        acc = fmaf(w, __ldg(vptr + (size_t)idx * DM_), acc);
                    }
                }
            }
        }
    }
    agg[(size_t)bn * DM_ + tid] = acc;
}

// ---------------- fused residual + LayerNorm (warp per row) ------------------
__global__ void addln_kernel(const float* __restrict__ X, const float* __restrict__ R,
                             const float* __restrict__ g, const float* __restrict__ bta,
                             float* __restrict__ out, int rows)
{
    int w    = (blockIdx.x * blockDim.x + threadIdx.x) >> 5;
    int lane = threadIdx.x & 31;
    if (w >= rows) return;
    const float* xp = X + (size_t)w * DM_;
    const float* rp = R + (size_t)w * DM_;
    int c0 = lane * 4, c1 = 128 + lane * 4;

    float4 x0 = *(const float4*)(xp + c0);
    float4 x1 = *(const float4*)(xp + c1);
    float4 r0 = *(const float4*)(rp + c0);
    float4 r1 = *(const float4*)(rp + c1);
    float v[8];
    v[0] = x0.x + r0.x; v[1] = x0.y + r0.y; v[2] = x0.z + r0.z; v[3] = x0.w + r0.w;
    v[4] = x1.x + r1.x; v[5] = x1.y + r1.y; v[6] = x1.z + r1.z; v[7] = x1.w + r1.w;

    float s = 0.f;
    #pragma unroll
    for (int i = 0; i < 8; i++) s += v[i];
    #pragma unroll
    for (int o = 16; o > 0; o >>= 1) s += __shfl_xor_sync(0xFFFFFFFFu, s, o);
    float mu = s * (1.f / 256.f);

    float q = 0.f;
    #pragma unroll
    for (int i = 0; i < 8; i++) { float d = v[i] - mu; q += d * d; }
    #pragma unroll
    for (int o = 16; o > 0; o >>= 1) q += __shfl_xor_sync(0xFFFFFFFFu, q, o);
    float rs = rsqrtf(q * (1.f / 256.f) + 1e-5f);

    float o0[4], o1[4];
    #pragma unroll
    for (int i = 0; i < 4; i++) {
        o0[i] = (v[i]     - mu) * rs * g[c0 + i] + bta[c0 + i];
        o1[i] = (v[4 + i] - mu) * rs * g[c1 + i] + bta[c1 + i];
    }
    *(float4*)(out + (size_t)w * DM_ + c0) = *(float4*)&o0[0];
    *(float4*)(out + (size_t)w * DM_ + c1) = *(float4*)&o1[0];
}

// ---------------- host orchestration -----------------------------------------
extern "C" void kernel_launch(void* const* d_in, const int* in_sizes, int n_in,
                              void* d_out, int out_size)
{
    const float* srcs[4] = {(const float*)d_in[0], (const float*)d_in[2],
                            (const float*)d_in[4], (const float*)d_in[6]};
    const float* poss[4] = {(const float*)d_in[1], (const float*)d_in[3],
                            (const float*)d_in[5], (const float*)d_in[7]};
    const float* lvl_emb = (const float*)d_in[8];
    const float* W_off  = (const float*)d_in[9],  *b_off  = (const float*)d_in[10];
    const float* W_attn = (const float*)d_in[11], *b_attn = (const float*)d_in[12];
    const float* W_val  = (const float*)d_in[13], *b_val  = (const float*)d_in[14];
    const float* W_out  = (const float*)d_in[15], *b_out  = (const float*)d_in[16];
    const float* ln1_g  = (const float*)d_in[17], *ln1_b  = (const float*)d_in[18];
    const float* W_ff1  = (const float*)d_in[19], *b_ff1  = (const float*)d_in[20];
    const float* W_ff2  = (const float*)d_in[21], *b_ff2  = (const float*)d_in[22];
    const float* ln2_g  = (const float*)d_in[23], *ln2_b  = (const float*)d_in[24];

    float *src_b, *pos_b, *val_b, *agg_b, *off_b, *attn_b, *ff_b;
    cudaGetSymbolAddress((void**)&src_b,  g_src);
    cudaGetSymbolAddress((void**)&pos_b,  g_pos);
    cudaGetSymbolAddress((void**)&val_b,  g_val);
    cudaGetSymbolAddress((void**)&agg_b,  g_agg);
    cudaGetSymbolAddress((void**)&off_b,  g_off);
    cudaGetSymbolAddress((void**)&attn_b, g_attn);
    cudaGetSymbolAddress((void**)&ff_b,   g_ff);

    const int sizes[4] = {16384, 2048, 256, 32};
    const int bases[4] = {0, 16384, 18432, 18688};
    for (int lv = 0; lv < 4; lv++) {
        dim3 gr((sizes[lv] + 31) / 32, DM_ / 32, BATCH);
        dim3 bl(32, 8);
        flatten_kernel<<<gr, bl>>>(srcs[lv], src_b, nullptr, sizes[lv], bases[lv]);
        flatten_kernel<<<gr, bl>>>(poss[lv], pos_b, lvl_emb + lv * DM_, sizes[lv], bases[lv]);
    }

    const int MT = (ROWS_ + 127) / 128;  // 293
    dim3 thr(256);
    for (int l = 0; l < 2; l++) {
        tgemm_kernel<<<dim3(2, MT), thr>>>(src_b, nullptr,
            W_val + (size_t)l * DM_ * DM_,  b_val + l * DM_,  val_b,  ROWS_, 256,  256, 0);
        tgemm_kernel<<<dim3(3, MT), thr>>>(src_b, pos_b,
            W_off + (size_t)l * DM_ * NOFF, b_off + l * NOFF, off_b,  ROWS_, NOFF, 256, 0);
        tgemm_kernel<<<dim3(1, MT), thr>>>(src_b, pos_b,
            W_attn + (size_t)l * DM_ * NATT, b_attn + l * NATT, attn_b, ROWS_, NATT, 256, 0);
        softmax_kernel<<<(ROWS_ * 8 + 255) / 256, 256>>>(attn_b, ROWS_ * 8);
        sample_kernel<<<ROWS_, 256>>>(val_b, off_b, attn_b, agg_b);
        tgemm_kernel<<<dim3(2, MT), thr>>>(agg_b, nullptr,
            W_out + (size_t)l * DM_ * DM_, b_out + l * DM_, val_b, ROWS_, 256, 256, 0);
        addln_kernel<<<(ROWS_ + 7) / 8, 256>>>(src_b, val_b,
            ln1_g + l * DM_, ln1_b + l * DM_, src_b, ROWS_);
        tgemm_kernel<<<dim3(8, MT), thr>>>(src_b, nullptr,
            W_ff1 + (size_t)l * DM_ * DFF_, b_ff1 + l * DFF_, ff_b, ROWS_, DFF_, 256, 1);
        tgemm_kernel<<<dim3(2, MT), thr>>>(ff_b, nullptr,
            W_ff2 + (size_t)l * DFF_ * DM_, b_ff2 + l * DM_, val_b, ROWS_, 256, DFF_, 0);
        float* dst = (l == 1) ? (float*)d_out : src_b;
        addln_kernel<<<(ROWS_ + 7) / 8, 256>>>(src_b, val_b,
            ln2_g + l * DM_, ln2_b + l * DM_, dst, ROWS_);
    }
}

// round 7
// speedup vs baseline: 1.6145x; 1.6145x over previous
#include <cuda_runtime.h>
#include <cstdint>
#include <math.h>

#define BATCH 2
#define DM_   256
#define LEN_  18720
#define ROWS_ (BATCH * LEN_)   // 37440
#define NOFF  384              // M*LV*P*3
#define NATT  128              // M*LV*P
#define DFF_  1024

// ---------------- scratch (static device globals; no allocs) ----------------
__device__ float g_src [(size_t)ROWS_ * DM_];
__device__ float g_pos [(size_t)ROWS_ * DM_];
__device__ float g_val [(size_t)ROWS_ * DM_];
__device__ float g_agg [(size_t)ROWS_ * DM_];
__device__ float g_off [(size_t)ROWS_ * NOFF];
__device__ float g_attn[(size_t)ROWS_ * NATT];
__device__ float g_ff  [(size_t)ROWS_ * DFF_];

// ---------------- helpers ----------------------------------------------------
__device__ __forceinline__ float to_tf32(float x) {
    uint32_t u;
    asm("cvt.rna.tf32.f32 %0, %1;" : "=r"(u) : "f"(x));
    return __uint_as_float(u);
}

__device__ __forceinline__ void mma_tf32(float* c, const uint32_t* a, const uint32_t* b) {
    asm volatile(
        "mma.sync.aligned.m16n8k8.row.col.f32.tf32.tf32.f32 "
        "{%0,%1,%2,%3},{%4,%5,%6,%7},{%8,%9},{%0,%1,%2,%3};"
        : "+f"(c[0]), "+f"(c[1]), "+f"(c[2]), "+f"(c[3])
        : "r"(a[0]), "r"(a[1]), "r"(a[2]), "r"(a[3]), "r"(b[0]), "r"(b[1]));
}

// ---------------- flatten + transpose: [B,DM,S] -> rows [b, base+s, c] -------
__global__ void flatten_kernel(const float* __restrict__ in, float* __restrict__ out,
                               const float* __restrict__ lvl_emb, int S, int base)
{
    __shared__ float tile[32][33];
    const int b  = blockIdx.z;
    const int s0 = blockIdx.x * 32;
    const int c0 = blockIdx.y * 32;
    const int tx = threadIdx.x, ty = threadIdx.y; // 32 x 8

    #pragma unroll
    for (int i = 0; i < 32; i += 8) {
        int c = c0 + ty + i, s = s0 + tx;
        float v = 0.f;
        if (s < S) v = in[((size_t)b * DM_ + c) * S + s];
        tile[ty + i][tx] = v;
    }
    __syncthreads();
    float emb = lvl_emb ? lvl_emb[c0 + tx] : 0.f;
    #pragma unroll
    for (int i = 0; i < 32; i += 8) {
        int s = s0 + ty + i, c = c0 + tx;
        if (s < S)
            out[((size_t)b * LEN_ + base + s) * DM_ + c] = tile[tx][ty + i] + emb;
    }
}

// ---------------- TF32 tensor-core GEMM, software-pipelined -------------------
// C[M,N] = (A (+A2)) @ W + bias, optional relu. Block 128x128, BK=16,
// 256 threads = 8 warps, warp tile 64x32 via m16n8k8 tf32 mma.
// Double-buffered smem; next slab LDGs issued before current slab's MMAs.
// B slab staged with one STS.128 per float4 (conflict-free) instead of 4 scalar STS.
__global__ __launch_bounds__(256) void tgemm_kernel(
    const float* __restrict__ A, const float* __restrict__ A2,
    const float* __restrict__ W, const float* __restrict__ bias,
    float* __restrict__ C, int Mrows, int N, int K, int relu)
{
    __shared__ float As[2][16][136];
    __shared__ float Bs[2][16][136];
    const int bm = blockIdx.y * 128;
    const int bn = blockIdx.x * 128;
    const int tid  = threadIdx.x;
    const int wid  = tid >> 5;
    const int lane = tid & 31;
    const int g    = lane >> 2;    // groupID 0..7
    const int t4   = lane & 3;     // thread-in-group 0..3
    const int wm   = (wid & 1) * 64;   // warp row base in tile
    const int wn   = (wid >> 1) * 32;  // warp col base in tile

    float acc[4][4][4];
    #pragma unroll
    for (int i = 0; i < 4; i++)
        #pragma unroll
        for (int j = 0; j < 4; j++)
            #pragma unroll
            for (int r = 0; r < 4; r++) acc[i][j][r] = 0.f;

    float4 pa[2], pb[2];

    // ---- load slab k0 into registers ----
    auto load_slab = [&](int k0) {
        #pragma unroll
        for (int t = 0; t < 2; t++) {
            int v   = tid + t * 256;
            int row = v >> 2;
            int c4  = (v & 3) * 4;
            int grow = bm + row;
            float4 av = make_float4(0.f, 0.f, 0.f, 0.f);
            if (grow < Mrows) {
                size_t gi = (size_t)grow * K + k0 + c4;
                av = *(const float4*)(A + gi);
                if (A2) {
                    float4 a2 = *(const float4*)(A2 + gi);
                    av.x += a2.x; av.y += a2.y; av.z += a2.z; av.w += a2.w;
                }
            }
            pa[t] = av;
        }
        #pragma unroll
        for (int t = 0; t < 2; t++) {
            int v  = tid + t * 256;
            int kr = v >> 5;
            int c4 = (v & 31) * 4;
            pb[t] = *(const float4*)(W + (size_t)(k0 + kr) * N + bn + c4);
        }
    };

    // ---- store registers into smem buffer (transpose A, tf32 round) ----
    auto store_slab = [&](int buf) {
        #pragma unroll
        for (int t = 0; t < 2; t++) {
            int v   = tid + t * 256;
            int row = v >> 2;
            int c4  = (v & 3) * 4;
            As[buf][c4 + 0][row] = to_tf32(pa[t].x);
            As[buf][c4 + 1][row] = to_tf32(pa[t].y);
            As[buf][c4 + 2][row] = to_tf32(pa[t].z);
            As[buf][c4 + 3][row] = to_tf32(pa[t].w);
        }
        #pragma unroll
        for (int t = 0; t < 2; t++) {
            int v  = tid + t * 256;
            int kr = v >> 5;
            int c4 = (v & 31) * 4;
            float4 cv;
            cv.x = to_tf32(pb[t].x);
            cv.y = to_tf32(pb[t].y);
            cv.z = to_tf32(pb[t].z);
            cv.w = to_tf32(pb[t].w);
            *(float4*)&Bs[buf][kr][c4] = cv;   // STS.128, lane-contiguous -> conflict-free
        }
    };

    // ---- compute one slab out of smem buffer ----
    auto compute_slab = [&](int buf) {
        #pragma unroll
        for (int ks = 0; ks < 16; ks += 8) {
            uint32_t af[4][4];
            #pragma unroll
            for (int mf = 0; mf < 4; mf++) {
                int mb = wm + mf * 16 + g;
                af[mf][0] = __float_as_uint(As[buf][ks + t4    ][mb    ]);
                af[mf][1] = __float_as_uint(As[buf][ks + t4    ][mb + 8]);
                af[mf][2] = __float_as_uint(As[buf][ks + t4 + 4][mb    ]);
                af[mf][3] = __float_as_uint(As[buf][ks + t4 + 4][mb + 8]);
            }
            uint32_t bf[4][2];
            #pragma unroll
            for (int nf = 0; nf < 4; nf++) {
                int nb = wn + nf * 8 + g;
                bf[nf][0] = __float_as_uint(Bs[buf][ks + t4    ][nb]);
                bf[nf][1] = __float_as_uint(Bs[buf][ks + t4 + 4][nb]);
            }
            #pragma unroll
            for (int mf = 0; mf < 4; mf++)
                #pragma unroll
                for (int nf = 0; nf < 4; nf++)
                    mma_tf32(acc[mf][nf], af[mf], bf[nf]);
        }
    };

    const int nslab = K >> 4;
    load_slab(0);
    store_slab(0);
    __syncthreads();

    for (int s = 0; s < nslab; s++) {
        int buf = s & 1;
        if (s + 1 < nslab) load_slab((s + 1) << 4);   // LDGs in flight during MMAs
        compute_slab(buf);
        if (s + 1 < nslab) store_slab(buf ^ 1);
        __syncthreads();
    }

    // ---- epilogue: bias (+relu), guarded stores ----
    #pragma unroll
    for (int mf = 0; mf < 4; mf++) {
        int row0 = bm + wm + mf * 16 + g;
        int row1 = row0 + 8;
        #pragma unroll
        for (int nf = 0; nf < 4; nf++) {
            int col = bn + wn + nf * 8 + 2 * t4;
            float b0 = bias[col], b1 = bias[col + 1];
            float v0 = acc[mf][nf][0] + b0;
            float v1 = acc[mf][nf][1] + b1;
            float v2 = acc[mf][nf][2] + b0;
            float v3 = acc[mf][nf][3] + b1;
            if (relu) {
                v0 = fmaxf(v0, 0.f); v1 = fmaxf(v1, 0.f);
                v2 = fmaxf(v2, 0.f); v3 = fmaxf(v3, 0.f);
            }
            if (row0 < Mrows) *(float2*)(C + (size_t)row0 * N + col) = make_float2(v0, v1);
            if (row1 < Mrows) *(float2*)(C + (size_t)row1 * N + col) = make_float2(v2, v3);
        }
    }
}

// ---------------- softmax over 16 (per b,n,m) --------------------------------
__global__ void softmax_kernel(float* __restrict__ attn, int total)
{
    int i = blockIdx.x * blockDim.x + threadIdx.x;
    if (i >= total) return;
    float* p = attn + (size_t)i * 16;
    float v[16];
    #pragma unroll
    for (int t = 0; t < 4; t++) {
        float4 f = *(float4*)(p + t * 4);
        v[t*4+0] = f.x; v[t*4+1] = f.y; v[t*4+2] = f.z; v[t*4+3] = f.w;
    }
    float mx = v[0];
    #pragma unroll
    for (int t = 1; t < 16; t++) mx = fmaxf(mx, v[t]);
    float s = 0.f;
    #pragma unroll
    for (int t = 0; t < 16; t++) { v[t] = expf(v[t] - mx); s += v[t]; }
    float inv = 1.f / s;
    #pragma unroll
    for (int t = 0; t < 4; t++) {
        float4 f = make_float4(v[t*4+0]*inv, v[t*4+1]*inv, v[t*4+2]*inv, v[t*4+3]*inv);
        *(float4*)(p + t * 4) = f;
    }
}

// ---------------- deformable trilinear sampling ------------------------------
__global__ __launch_bounds__(256) void sample_kernel(
    const float* __restrict__ value, const float* __restrict__ off,
    const float* __restrict__ attn, float* __restrict__ agg)
{
    const int bn = blockIdx.x;
    const int b  = bn / LEN_;
    const int n  = bn - b * LEN_;
    const int tid = threadIdx.x;
    const int m  = tid >> 5, dh = tid & 31;

    float rc0, rc1, rc2;
    {
        int s, z, r, y, x;
        if (n < 16384)      { s = n;         z = s >> 10; r = s & 1023; y = r >> 5; x = r & 31;
            rc0 = (z + .5f) * (1.f/16.f); rc1 = (y + .5f) * (1.f/32.f); rc2 = (x + .5f) * (1.f/32.f); }
        else if (n < 18432) { s = n - 16384; z = s >> 8;  r = s & 255;  y = r >> 4; x = r & 15;
            rc0 = (z + .5f) * (1.f/8.f);  rc1 = (y + .5f) * (1.f/16.f); rc2 = (x + .5f) * (1.f/16.f); }
        else if (n < 18688) { s = n - 18432; z = s >> 6;  r = s & 63;   y = r >> 3; x = r & 7;
            rc0 = (z + .5f) * (1.f/4.f);  rc1 = (y + .5f) * (1.f/8.f);  rc2 = (x + .5f) * (1.f/8.f); }
        else                { s = n - 18688; z = s >> 4;  r = s & 15;   y = r >> 2; x = r & 3;
            rc0 = (z + .5f) * .5f;        rc1 = (y + .5f) * .25f;       rc2 = (x + .5f) * .25f; }
    }

    const float* offp = off  + ((size_t)bn * 8 + m) * 48;
    const float* attp = attn + ((size_t)bn * 8 + m) * 16;

    const int LD[4] = {16, 8, 4, 2};
    const int LH[4] = {32, 16, 8, 4};
    const int LW[4] = {32, 16, 8, 4};
    const int LB[4] = {0, 16384, 18432, 18688};

    float acc = 0.f;
    #pragma unroll
    for (int lvl = 0; lvl < 4; lvl++) {
        const int D = LD[lvl], H = LH[lvl], Wd = LW[lvl];
        const float* vptr = value + ((size_t)b * LEN_ + LB[lvl]) * DM_ + m * 32 + dh;
        #pragma unroll
        for (int p = 0; p < 4; p++) {
            float o0 = __ldg(offp + lvl * 12 + p * 3 + 0);
            float o1 = __ldg(offp + lvl * 12 + p * 3 + 1);
            float o2 = __ldg(offp + lvl * 12 + p * 3 + 2);
            float a  = __ldg(attp + lvl * 4 + p);
            float x = fmaf(rc0, (float)Wd, o0) - 0.5f;
            float y = fmaf(rc1, (float)H,  o1) - 0.5f;
            float z = fmaf(rc2, (float)D,  o2) - 0.5f;
            float xf = floorf(x), yf = floorf(y), zf = floorf(z);
            float fx = x - xf, fy = y - yf, fz = z - zf;
            int x0 = (int)xf, y0 = (int)yf, z0 = (int)zf;
            float wx0 = (1.f - fx) * a, wx1 = fx * a;
            float wy0 = 1.f - fy,       wy1 = fy;
            float wz0 = 1.f - fz,       wz1 = fz;
            #pragma unroll
            for (int dz = 0; dz < 2; dz++) {
                int zi = z0 + dz;
                if ((unsigned)zi >= (unsigned)D) continue;
                float wz_ = dz ? wz1 : wz0;
                #pragma unroll
                for (int dy = 0; dy < 2; dy++) {
                    int yi = y0 + dy;
                    if ((unsigned)yi >= (unsigned)H) continue;
                    float wzy = wz_ * (dy ? wy1 : wy0);
                    #pragma unroll
                    for (int dx = 0; dx < 2; dx++) {
                        int xi = x0 + dx;
                        if ((unsigned)xi >= (unsigned)Wd) continue;
                        float w = wzy * (dx ? wx1 : wx0);
                        int idx = (zi * H + yi) * Wd + xi;
                        acc = fmaf(w, __ldg(vptr + (size_t)idx * DM_), acc);
                    }
                }
            }
        }
    }
    agg[(size_t)bn * DM_ + tid] = acc;
}

// ---------------- fused residual + LayerNorm (warp per row) ------------------
__global__ void addln_kernel(const float* __restrict__ X, const float* __restrict__ R,
                             const float* __restrict__ g, const float* __restrict__ bta,
                             float* __restrict__ out, int rows)
{
    int w    = (blockIdx.x * blockDim.x + threadIdx.x) >> 5;
    int lane = threadIdx.x & 31;
    if (w >= rows) return;
    const float* xp = X + (size_t)w * DM_;
    const float* rp = R + (size_t)w * DM_;
    int c0 = lane * 4, c1 = 128 + lane * 4;

    float4 x0 = *(const float4*)(xp + c0);
    float4 x1 = *(const float4*)(xp + c1);
    float4 r0 = *(const float4*)(rp + c0);
    float4 r1 = *(const float4*)(rp + c1);
    float v[8];
    v[0] = x0.x + r0.x; v[1] = x0.y + r0.y; v[2] = x0.z + r0.z; v[3] = x0.w + r0.w;
    v[4] = x1.x + r1.x; v[5] = x1.y + r1.y; v[6] = x1.z + r1.z; v[7] = x1.w + r1.w;

    float s = 0.f;
    #pragma unroll
    for (int i = 0; i < 8; i++) s += v[i];
    #pragma unroll
    for (int o = 16; o > 0; o >>= 1) s += __shfl_xor_sync(0xFFFFFFFFu, s, o);
    float mu = s * (1.f / 256.f);

    float q = 0.f;
    #pragma unroll
    for (int i = 0; i < 8; i++) { float d = v[i] - mu; q += d * d; }
    #pragma unroll
    for (int o = 16; o > 0; o >>= 1) q += __shfl_xor_sync(0xFFFFFFFFu, q, o);
    float rs = rsqrtf(q * (1.f / 256.f) + 1e-5f);

    float o0[4], o1[4];
    #pragma unroll
    for (int i = 0; i < 4; i++) {
        o0[i] = (v[i]     - mu) * rs * g[c0 + i] + bta[c0 + i];
        o1[i] = (v[4 + i] - mu) * rs * g[c1 + i] + bta[c1 + i];
    }
    *(float4*)(out + (size_t)w * DM_ + c0) = *(float4*)&o0[0];
    *(float4*)(out + (size_t)w * DM_ + c1) = *(float4*)&o1[0];
}

// ---------------- host orchestration -----------------------------------------
extern "C" void kernel_launch(void* const* d_in, const int* in_sizes, int n_in,
                              void* d_out, int out_size)
{
    const float* srcs[4] = {(const float*)d_in[0], (const float*)d_in[2],
                            (const float*)d_in[4], (const float*)d_in[6]};
    const float* poss[4] = {(const float*)d_in[1], (const float*)d_in[3],
                            (const float*)d_in[5], (const float*)d_in[7]};
    const float* lvl_emb = (const float*)d_in[8];
    const float* W_off  = (const float*)d_in[9],  *b_off  = (const float*)d_in[10];
    const float* W_attn = (const float*)d_in[11], *b_attn = (const float*)d_in[12];
    const float* W_val  = (const float*)d_in[13], *b_val  = (const float*)d_in[14];
    const float* W_out  = (const float*)d_in[15], *b_out  = (const float*)d_in[16];
    const float* ln1_g  = (const float*)d_in[17], *ln1_b  = (const float*)d_in[18];
    const float* W_ff1  = (const float*)d_in[19], *b_ff1  = (const float*)d_in[20];
    const float* W_ff2  = (const float*)d_in[21], *b_ff2  = (const float*)d_in[22];
    const float* ln2_g  = (const float*)d_in[23], *ln2_b  = (const float*)d_in[24];

    float *src_b, *pos_b, *val_b, *agg_b, *off_b, *attn_b, *ff_b;
    cudaGetSymbolAddress((void**)&src_b,  g_src);
    cudaGetSymbolAddress((void**)&pos_b,  g_pos);
    cudaGetSymbolAddress((void**)&val_b,  g_val);
    cudaGetSymbolAddress((void**)&agg_b,  g_agg);
    cudaGetSymbolAddress((void**)&off_b,  g_off);
    cudaGetSymbolAddress((void**)&attn_b, g_attn);
    cudaGetSymbolAddress((void**)&ff_b,   g_ff);

    const int sizes[4] = {16384, 2048, 256, 32};
    const int bases[4] = {0, 16384, 18432, 18688};
    for (int lv = 0; lv < 4; lv++) {
        dim3 gr((sizes[lv] + 31) / 32, DM_ / 32, BATCH);
        dim3 bl(32, 8);
        flatten_kernel<<<gr, bl>>>(srcs[lv], src_b, nullptr, sizes[lv], bases[lv]);
        flatten_kernel<<<gr, bl>>>(poss[lv], pos_b, lvl_emb + lv * DM_, sizes[lv], bases[lv]);
    }

    const int MT = (ROWS_ + 127) / 128;  // 293
    dim3 thr(256);
    for (int l = 0; l < 2; l++) {
        tgemm_kernel<<<dim3(2, MT), thr>>>(src_b, nullptr,
            W_val + (size_t)l * DM_ * DM_,  b_val + l * DM_,  val_b,  ROWS_, 256,  256, 0);
        tgemm_kernel<<<dim3(3, MT), thr>>>(src_b, pos_b,
            W_off + (size_t)l * DM_ * NOFF, b_off + l * NOFF, off_b,  ROWS_, NOFF, 256, 0);
        tgemm_kernel<<<dim3(1, MT), thr>>>(src_b, pos_b,
            W_attn + (size_t)l * DM_ * NATT, b_attn + l * NATT, attn_b, ROWS_, NATT, 256, 0);
        softmax_kernel<<<(ROWS_ * 8 + 255) / 256, 256>>>(attn_b, ROWS_ * 8);
        sample_kernel<<<ROWS_, 256>>>(val_b, off_b, attn_b, agg_b);
        tgemm_kernel<<<dim3(2, MT), thr>>>(agg_b, nullptr,
            W_out + (size_t)l * DM_ * DM_, b_out + l * DM_, val_b, ROWS_, 256, 256, 0);
        addln_kernel<<<(ROWS_ + 7) / 8, 256>>>(src_b, val_b,
            ln1_g + l * DM_, ln1_b + l * DM_, src_b, ROWS_);
        tgemm_kernel<<<dim3(8, MT), thr>>>(src_b, nullptr,
            W_ff1 + (size_t)l * DM_ * DFF_, b_ff1 + l * DFF_, ff_b, ROWS_, DFF_, 256, 1);
        tgemm_kernel<<<dim3(2, MT), thr>>>(ff_b, nullptr,
            W_ff2 + (size_t)l * DFF_ * DM_, b_ff2 + l * DM_, val_b, ROWS_, 256, DFF_, 0);
        float* dst = (l == 1) ? (float*)d_out : src_b;
        addln_kernel<<<(ROWS_ + 7) / 8, 256>>>(src_b, val_b,
            ln2_g + l * DM_, ln2_b + l * DM_, dst, ROWS_);
    }
}

// round 8
// speedup vs baseline: 1.6242x; 1.0060x over previous
#include <cuda_runtime.h>
#include <cstdint>
#include <math.h>

#define BATCH 2
#define DM_   256
#define LEN_  18720
#define ROWS_ (BATCH * LEN_)   // 37440
#define NOFF  384              // M*LV*P*3
#define NATT  128              // M*LV*P
#define DFF_  1024

// ---------------- scratch (static device globals; no allocs) ----------------
__device__ float g_src [(size_t)ROWS_ * DM_];
__device__ float g_pos [(size_t)ROWS_ * DM_];
__device__ float g_val [(size_t)ROWS_ * DM_];
__device__ float g_agg [(size_t)ROWS_ * DM_];
__device__ float g_off [(size_t)ROWS_ * NOFF];
__device__ float g_attn[(size_t)ROWS_ * NATT];
__device__ float g_ff  [(size_t)ROWS_ * DFF_];

// ---------------- helpers ----------------------------------------------------
__device__ __forceinline__ float to_tf32(float x) {
    uint32_t u;
    asm("cvt.rna.tf32.f32 %0, %1;" : "=r"(u) : "f"(x));
    return __uint_as_float(u);
}

__device__ __forceinline__ void mma_tf32(float* c, const uint32_t* a, const uint32_t* b) {
    asm volatile(
        "mma.sync.aligned.m16n8k8.row.col.f32.tf32.tf32.f32 "
        "{%0,%1,%2,%3},{%4,%5,%6,%7},{%8,%9},{%0,%1,%2,%3};"
        : "+f"(c[0]), "+f"(c[1]), "+f"(c[2]), "+f"(c[3])
        : "r"(a[0]), "r"(a[1]), "r"(a[2]), "r"(a[3]), "r"(b[0]), "r"(b[1]));
}

// -------- fused flatten+transpose for src AND pos: [B,DM,S] -> rows ----------
__global__ void flatten2_kernel(const float* __restrict__ in_src, const float* __restrict__ in_pos,
                                float* __restrict__ out_src, float* __restrict__ out_pos,
                                const float* __restrict__ lvl_emb, int S, int base)
{
    __shared__ float tile[32][33];
    const int b  = blockIdx.z;
    const int s0 = blockIdx.x * 32;
    const int c0 = blockIdx.y * 32;
    const int tx = threadIdx.x, ty = threadIdx.y; // 32 x 8

    // ---- src (no embedding) ----
    #pragma unroll
    for (int i = 0; i < 32; i += 8) {
        int c = c0 + ty + i, s = s0 + tx;
        float v = 0.f;
        if (s < S) v = in_src[((size_t)b * DM_ + c) * S + s];
        tile[ty + i][tx] = v;
    }
    __syncthreads();
    #pragma unroll
    for (int i = 0; i < 32; i += 8) {
        int s = s0 + ty + i, c = c0 + tx;
        if (s < S)
            out_src[((size_t)b * LEN_ + base + s) * DM_ + c] = tile[tx][ty + i];
    }
    __syncthreads();
    // ---- pos (+ level embedding) ----
    #pragma unroll
    for (int i = 0; i < 32; i += 8) {
        int c = c0 + ty + i, s = s0 + tx;
        float v = 0.f;
        if (s < S) v = in_pos[((size_t)b * DM_ + c) * S + s];
        tile[ty + i][tx] = v;
    }
    __syncthreads();
    float emb = lvl_emb[c0 + tx];
    #pragma unroll
    for (int i = 0; i < 32; i += 8) {
        int s = s0 + ty + i, c = c0 + tx;
        if (s < S)
            out_pos[((size_t)b * LEN_ + base + s) * DM_ + c] = tile[tx][ty + i] + emb;
    }
}

// ---------------- TF32 tensor-core GEMM, software-pipelined -------------------
// Block 128x128, BK=16, 256 threads = 8 warps, warp tile 64x32 (m16n8k8).
// A staged ROW-MAJOR [128][20] (STS.128 stores, conflict-free scalar loads).
// B staged [16][136] with STS.128. Double-buffered; next-slab LDGs before MMAs.
__global__ __launch_bounds__(256) void tgemm_kernel(
    const float* __restrict__ A, const float* __restrict__ A2,
    const float* __restrict__ W, const float* __restrict__ bias,
    float* __restrict__ C, int Mrows, int N, int K, int relu)
{
    __shared__ float As[2][128][20];
    __shared__ float Bs[2][16][136];
    const int bm = blockIdx.y * 128;
    const int bn = blockIdx.x * 128;
    const int tid  = threadIdx.x;
    const int wid  = tid >> 5;
    const int lane = tid & 31;
    const int g    = lane >> 2;    // groupID 0..7
    const int t4   = lane & 3;     // thread-in-group 0..3
    const int wm   = (wid & 1) * 64;   // warp row base in tile
    const int wn   = (wid >> 1) * 32;  // warp col base in tile

    float acc[4][4][4];
    #pragma unroll
    for (int i = 0; i < 4; i++)
        #pragma unroll
        for (int j = 0; j < 4; j++)
            #pragma unroll
            for (int r = 0; r < 4; r++) acc[i][j][r] = 0.f;

    float4 pa[2], pb[2];

    auto load_slab = [&](int k0) {
        #pragma unroll
        for (int t = 0; t < 2; t++) {
            int v   = tid + t * 256;
            int row = v >> 2;
            int c4  = (v & 3) * 4;
            int grow = bm + row;
            float4 av = make_float4(0.f, 0.f, 0.f, 0.f);
            if (grow < Mrows) {
                size_t gi = (size_t)grow * K + k0 + c4;
                av = *(const float4*)(A + gi);
                if (A2) {
                    float4 a2 = *(const float4*)(A2 + gi);
                    av.x += a2.x; av.y += a2.y; av.z += a2.z; av.w += a2.w;
                }
            }
            pa[t] = av;
        }
        #pragma unroll
        for (int t = 0; t < 2; t++) {
            int v  = tid + t * 256;
            int kr = v >> 5;
            int c4 = (v & 31) * 4;
            pb[t] = *(const float4*)(W + (size_t)(k0 + kr) * N + bn + c4);
        }
    };

    auto store_slab = [&](int buf) {
        #pragma unroll
        for (int t = 0; t < 2; t++) {
            int v   = tid + t * 256;
            int row = v >> 2;
            int c4  = (v & 3) * 4;
            float4 cv;
            cv.x = to_tf32(pa[t].x);
            cv.y = to_tf32(pa[t].y);
            cv.z = to_tf32(pa[t].z);
            cv.w = to_tf32(pa[t].w);
            *(float4*)&As[buf][row][c4] = cv;   // STS.128, uniform banks
        }
        #pragma unroll
        for (int t = 0; t < 2; t++) {
            int v  = tid + t * 256;
            int kr = v >> 5;
            int c4 = (v & 31) * 4;
            float4 cv;
            cv.x = to_tf32(pb[t].x);
            cv.y = to_tf32(pb[t].y);
            cv.z = to_tf32(pb[t].z);
            cv.w = to_tf32(pb[t].w);
            *(float4*)&Bs[buf][kr][c4] = cv;    // STS.128, conflict-free
        }
    };

    auto compute_slab = [&](int buf) {
        #pragma unroll
        for (int ks = 0; ks < 16; ks += 8) {
            uint32_t af[4][4];
            #pragma unroll
            for (int mf = 0; mf < 4; mf++) {
                int mb = wm + mf * 16 + g;
                af[mf][0] = __float_as_uint(As[buf][mb    ][ks + t4    ]);
                af[mf][1] = __float_as_uint(As[buf][mb + 8][ks + t4    ]);
                af[mf][2] = __float_as_uint(As[buf][mb    ][ks + t4 + 4]);
                af[mf][3] = __float_as_uint(As[buf][mb + 8][ks + t4 + 4]);
            }
            uint32_t bf[4][2];
            #pragma unroll
            for (int nf = 0; nf < 4; nf++) {
                int nb = wn + nf * 8 + g;
                bf[nf][0] = __float_as_uint(Bs[buf][ks + t4    ][nb]);
                bf[nf][1] = __float_as_uint(Bs[buf][ks + t4 + 4][nb]);
            }
            #pragma unroll
            for (int mf = 0; mf < 4; mf++)
                #pragma unroll
                for (int nf = 0; nf < 4; nf++)
                    mma_tf32(acc[mf][nf], af[mf], bf[nf]);
        }
    };

    const int nslab = K >> 4;
    load_slab(0);
    store_slab(0);
    __syncthreads();

    for (int s = 0; s < nslab; s++) {
        int buf = s & 1;
        if (s + 1 < nslab) load_slab((s + 1) << 4);
        compute_slab(buf);
        if (s + 1 < nslab) store_slab(buf ^ 1);
        __syncthreads();
    }

    // ---- epilogue: bias (+relu), guarded stores ----
    #pragma unroll
    for (int mf = 0; mf < 4; mf++) {
        int row0 = bm + wm + mf * 16 + g;
        int row1 = row0 + 8;
        #pragma unroll
        for (int nf = 0; nf < 4; nf++) {
            int col = bn + wn + nf * 8 + 2 * t4;
            float b0 = bias[col], b1 = bias[col + 1];
            float v0 = acc[mf][nf][0] + b0;
            float v1 = acc[mf][nf][1] + b1;
            float v2 = acc[mf][nf][2] + b0;
            float v3 = acc[mf][nf][3] + b1;
            if (relu) {
                v0 = fmaxf(v0, 0.f); v1 = fmaxf(v1, 0.f);
                v2 = fmaxf(v2, 0.f); v3 = fmaxf(v3, 0.f);
            }
            if (row0 < Mrows) *(float2*)(C + (size_t)row0 * N + col) = make_float2(v0, v1);
            if (row1 < Mrows) *(float2*)(C + (size_t)row1 * N + col) = make_float2(v2, v3);
        }
    }
}

// ---------------- softmax over 16 (per b,n,m) --------------------------------
__global__ void softmax_kernel(float* __restrict__ attn, int total)
{
    int i = blockIdx.x * blockDim.x + threadIdx.x;
    if (i >= total) return;
    float* p = attn + (size_t)i * 16;
    float v[16];
    #pragma unroll
    for (int t = 0; t < 4; t++) {
        float4 f = *(float4*)(p + t * 4);
        v[t*4+0] = f.x; v[t*4+1] = f.y; v[t*4+2] = f.z; v[t*4+3] = f.w;
    }
    float mx = v[0];
    #pragma unroll
    for (int t = 1; t < 16; t++) mx = fmaxf(mx, v[t]);
    float s = 0.f;
    #pragma unroll
    for (int t = 0; t < 16; t++) { v[t] = expf(v[t] - mx); s += v[t]; }
    float inv = 1.f / s;
    #pragma unroll
    for (int t = 0; t < 4; t++) {
        float4 f = make_float4(v[t*4+0]*inv, v[t*4+1]*inv, v[t*4+2]*inv, v[t*4+3]*inv);
        *(float4*)(p + t * 4) = f;
    }
}

// ---------------- deformable trilinear sampling ------------------------------
__global__ __launch_bounds__(256) void sample_kernel(
    const float* __restrict__ value, const float* __restrict__ off,
    const float* __restrict__ attn, float* __restrict__ agg)
{
    const int bn = blockIdx.x;
    const int b  = bn / LEN_;
    const int n  = bn - b * LEN_;
    const int tid = threadIdx.x;
    const int m  = tid >> 5, dh = tid & 31;

    float rc0, rc1, rc2;
    {
        int s, z, r, y, x;
        if (n < 16384)      { s = n;         z = s >> 10; r = s & 1023; y = r >> 5; x = r & 31;
            rc0 = (z + .5f) * (1.f/16.f); rc1 = (y + .5f) * (1.f/32.f); rc2 = (x + .5f) * (1.f/32.f); }
        else if (n < 18432) { s = n - 16384; z = s >> 8;  r = s & 255;  y = r >> 4; x = r & 15;
            rc0 = (z + .5f) * (1.f/8.f);  rc1 = (y + .5f) * (1.f/16.f); rc2 = (x + .5f) * (1.f/16.f); }
        else if (n < 18688) { s = n - 18432; z = s >> 6;  r = s & 63;   y = r >> 3; x = r & 7;
            rc0 = (z + .5f) * (1.f/4.f);  rc1 = (y + .5f) * (1.f/8.f);  rc2 = (x + .5f) * (1.f/8.f); }
        else                { s = n - 18688; z = s >> 4;  r = s & 15;   y = r >> 2; x = r & 3;
            rc0 = (z + .5f) * .5f;        rc1 = (y + .5f) * .25f;       rc2 = (x + .5f) * .25f; }
    }

    const float* offp = off  + ((size_t)bn * 8 + m) * 48;
    const float* attp = attn + ((size_t)bn * 8 + m) * 16;

    const int LD[4] = {16, 8, 4, 2};
    const int LH[4] = {32, 16, 8, 4};
    const int LW[4] = {32, 16, 8, 4};
    const int LB[4] = {0, 16384, 18432, 18688};

    float acc0 = 0.f, acc1 = 0.f;   // split accumulator chain
    #pragma unroll
    for (int lvl = 0; lvl < 4; lvl++) {
        const int D = LD[lvl], H = LH[lvl], Wd = LW[lvl];
        const float* vptr = value + ((size_t)b * LEN_ + LB[lvl]) * DM_ + m * 32 + dh;
        #pragma unroll
        for (int p = 0; p < 4; p++) {
            float o0 = __ldg(offp + lvl * 12 + p * 3 + 0);
            float o1 = __ldg(offp + lvl * 12 + p * 3 + 1);
            float o2 = __ldg(offp + lvl * 12 + p * 3 + 2);
            float a  = __ldg(attp + lvl * 4 + p);
            float x = fmaf(rc0, (float)Wd, o0) - 0.5f;
            float y = fmaf(rc1, (float)H,  o1) - 0.5f;
            float z = fmaf(rc2, (float)D,  o2) - 0.5f;
            float xf = floorf(x), yf = floorf(y), zf = floorf(z);
            float fx = x - xf, fy = y - yf, fz = z - zf;
            int x0 = (int)xf, y0 = (int)yf, z0 = (int)zf;
            float wx0 = (1.f - fx) * a, wx1 = fx * a;
            float wy0 = 1.f - fy,       wy1 = fy;
            float wz0 = 1.f - fz,       wz1 = fz;
            #pragma unroll
            for (int dz = 0; dz < 2; dz++) {
                int zi = z0 + dz;
                if ((unsigned)zi >= (unsigned)D) continue;
                float wz_ = dz ? wz1 : wz0;
                #pragma unroll
                for (int dy = 0; dy < 2; dy++) {
                    int yi = y0 + dy;
                    if ((unsigned)yi >= (unsigned)H) continue;
                    float wzy = wz_ * (dy ? wy1 : wy0);
                    #pragma unroll
                    for (int dx = 0; dx < 2; dx++) {
                        int xi = x0 + dx;
                        if ((unsigned)xi >= (unsigned)Wd) continue;
                        float w = wzy * (dx ? wx1 : wx0);
                        int idx = (zi * H + yi) * Wd + xi;
                        float vv = __ldg(vptr + (size_t)idx * DM_);
                        if (dz) acc1 = fmaf(w, vv, acc1);
                        else    acc0 = fmaf(w, vv, acc0);
                    }
                }
            }
        }
    }
    agg[(size_t)bn * DM_ + tid] = acc0 + acc1;
}

// ---------------- fused residual + LayerNorm (warp per row) ------------------
__global__ void addln_kernel(const float* __restrict__ X, const float* __restrict__ R,
                             const float* __restrict__ g, const float* __restrict__ bta,
                             float* __restrict__ out, int rows)
{
    int w    = (blockIdx.x * blockDim.x + threadIdx.x) >> 5;
    int lane = threadIdx.x & 31;
    if (w >= rows) return;
    const float* xp = X + (size_t)w * DM_;
    const float* rp = R + (size_t)w * DM_;
    int c0 = lane * 4, c1 = 128 + lane * 4;

    float4 x0 = *(const float4*)(xp + c0);
    float4 x1 = *(const float4*)(xp + c1);
    float4 r0 = *(const float4*)(rp + c0);
    float4 r1 = *(const float4*)(rp + c1);
    float v[8];
    v[0] = x0.x + r0.x; v[1] = x0.y + r0.y; v[2] = x0.z + r0.z; v[3] = x0.w + r0.w;
    v[4] = x1.x + r1.x; v[5] = x1.y + r1.y; v[6] = x1.z + r1.z; v[7] = x1.w + r1.w;

    float s = 0.f;
    #pragma unroll
    for (int i = 0; i < 8; i++) s += v[i];
    #pragma unroll
    for (int o = 16; o > 0; o >>= 1) s += __shfl_xor_sync(0xFFFFFFFFu, s, o);
    float mu = s * (1.f / 256.f);

    float q = 0.f;
    #pragma unroll
    for (int i = 0; i < 8; i++) { float d = v[i] - mu; q += d * d; }
    #pragma unroll
    for (int o = 16; o > 0; o >>= 1) q += __shfl_xor_sync(0xFFFFFFFFu, q, o);
    float rs = rsqrtf(q * (1.f / 256.f) + 1e-5f);

    float o0[4], o1[4];
    #pragma unroll
    for (int i = 0; i < 4; i++) {
        o0[i] = (v[i]     - mu) * rs * g[c0 + i] + bta[c0 + i];
        o1[i] = (v[4 + i] - mu) * rs * g[c1 + i] + bta[c1 + i];
    }
    *(float4*)(out + (size_t)w * DM_ + c0) = *(float4*)&o0[0];
    *(float4*)(out + (size_t)w * DM_ + c1) = *(float4*)&o1[0];
}

// ---------------- host orchestration -----------------------------------------
extern "C" void kernel_launch(void* const* d_in, const int* in_sizes, int n_in,
                              void* d_out, int out_size)
{
    const float* srcs[4] = {(const float*)d_in[0], (const float*)d_in[2],
                            (const float*)d_in[4], (const float*)d_in[6]};
    const float* poss[4] = {(const float*)d_in[1], (const float*)d_in[3],
                            (const float*)d_in[5], (const float*)d_in[7]};
    const float* lvl_emb = (const float*)d_in[8];
    const float* W_off  = (const float*)d_in[9],  *b_off  = (const float*)d_in[10];
    const float* W_attn = (const float*)d_in[11], *b_attn = (const float*)d_in[12];
    const float* W_val  = (const float*)d_in[13], *b_val  = (const float*)d_in[14];
    const float* W_out  = (const float*)d_in[15], *b_out  = (const float*)d_in[16];
    const float* ln1_g  = (const float*)d_in[17], *ln1_b  = (const float*)d_in[18];
    const float* W_ff1  = (const float*)d_in[19], *b_ff1  = (const float*)d_in[20];
    const float* W_ff2  = (const float*)d_in[21], *b_ff2  = (const float*)d_in[22];
    const float* ln2_g  = (const float*)d_in[23], *ln2_b  = (const float*)d_in[24];

    float *src_b, *pos_b, *val_b, *agg_b, *off_b, *attn_b, *ff_b;
    cudaGetSymbolAddress((void**)&src_b,  g_src);
    cudaGetSymbolAddress((void**)&pos_b,  g_pos);
    cudaGetSymbolAddress((void**)&val_b,  g_val);
    cudaGetSymbolAddress((void**)&agg_b,  g_agg);
    cudaGetSymbolAddress((void**)&off_b,  g_off);
    cudaGetSymbolAddress((void**)&attn_b, g_attn);
    cudaGetSymbolAddress((void**)&ff_b,   g_ff);

    const int sizes[4] = {16384, 2048, 256, 32};
    const int bases[4] = {0, 16384, 18432, 18688};
    for (int lv = 0; lv < 4; lv++) {
        dim3 gr((sizes[lv] + 31) / 32, DM_ / 32, BATCH);
        dim3 bl(32, 8);
        flatten2_kernel<<<gr, bl>>>(srcs[lv], poss[lv], src_b, pos_b,
                                    lvl_emb + lv * DM_, sizes[lv], bases[lv]);
    }

    const int MT = (ROWS_ + 127) / 128;  // 293
    dim3 thr(256);
    for (int l = 0; l < 2; l++) {
        tgemm_kernel<<<dim3(2, MT), thr>>>(src_b, nullptr,
            W_val + (size_t)l * DM_ * DM_,  b_val + l * DM_,  val_b,  ROWS_, 256,  256, 0);
        tgemm_kernel<<<dim3(3, MT), thr>>>(src_b, pos_b,
            W_off + (size_t)l * DM_ * NOFF, b_off + l * NOFF, off_b,  ROWS_, NOFF, 256, 0);
        tgemm_kernel<<<dim3(1, MT), thr>>>(src_b, pos_b,
            W_attn + (size_t)l * DM_ * NATT, b_attn + l * NATT, attn_b, ROWS_, NATT, 256, 0);
        softmax_kernel<<<(ROWS_ * 8 + 255) / 256, 256>>>(attn_b, ROWS_ * 8);
        sample_kernel<<<ROWS_, 256>>>(val_b, off_b, attn_b, agg_b);
        tgemm_kernel<<<dim3(2, MT), thr>>>(agg_b, nullptr,
            W_out + (size_t)l * DM_ * DM_, b_out + l * DM_, val_b, ROWS_, 256, 256, 0);
        addln_kernel<<<(ROWS_ + 7) / 8, 256>>>(src_b, val_b,
            ln1_g + l * DM_, ln1_b + l * DM_, src_b, ROWS_);
        tgemm_kernel<<<dim3(8, MT), thr>>>(src_b, nullptr,
            W_ff1 + (size_t)l * DM_ * DFF_, b_ff1 + l * DFF_, ff_b, ROWS_, DFF_, 256, 1);
        tgemm_kernel<<<dim3(2, MT), thr>>>(ff_b, nullptr,
            W_ff2 + (size_t)l * DFF_ * DM_, b_ff2 + l * DM_, val_b, ROWS_, 256, DFF_, 0);
        float* dst = (l == 1) ? (float*)d_out : src_b;
        addln_kernel<<<(ROWS_ + 7) / 8, 256>>>(src_b, val_b,
            ln2_g + l * DM_, ln2_b + l * DM_, dst, ROWS_);
    }
}

// round 10
// speedup vs baseline: 1.7449x; 1.0743x over previous
#include <cuda_runtime.h>
#include <cstdint>
#include <math.h>

#define BATCH 2
#define DM_   256
#define LEN_  18720
#define ROWS_ (BATCH * LEN_)   // 37440
#define NOFF  384
#define NATT  128
#define DFF_  1024

// GEMM tiling
#define BK 32
#define NSTAGE 3
#define A_STRIDE 36
#define B_STRIDE 136
#define A_SZ (128 * A_STRIDE)          // 4608 floats
#define B_SZ (BK * B_STRIDE)           // 4352 floats
#define STG_SZ (A_SZ + B_SZ)           // 8960 floats
#define SMEM_BYTES (NSTAGE * STG_SZ * 4)  // 107520 B

// ---------------- scratch (static device globals; no allocs) ----------------
__device__ float g_src [(size_t)ROWS_ * DM_];
__device__ float g_srcr[(size_t)ROWS_ * DM_];   // rna(src)
__device__ float g_qr  [(size_t)ROWS_ * DM_];   // rna(src+pos)
__device__ float g_pos [(size_t)ROWS_ * DM_];
__device__ float g_val [(size_t)ROWS_ * DM_];
__device__ float g_agg [(size_t)ROWS_ * DM_];
__device__ float g_off [(size_t)ROWS_ * NOFF];
__device__ float g_attn[(size_t)ROWS_ * NATT];
__device__ float g_ff  [(size_t)ROWS_ * DFF_];
__device__ float g_w   [1572864];               // rounded weights, all layers

// ---------------- helpers ----------------------------------------------------
__device__ __forceinline__ float to_tf32(float x) {
    uint32_t u;
    asm("cvt.rna.tf32.f32 %0, %1;" : "=r"(u) : "f"(x));
    return __uint_as_float(u);
}

__device__ __forceinline__ void mma_tf32(float* c, const uint32_t* a, const uint32_t* b) {
    asm volatile(
        "mma.sync.aligned.m16n8k8.row.col.f32.tf32.tf32.f32 "
        "{%0,%1,%2,%3},{%4,%5,%6,%7},{%8,%9},{%0,%1,%2,%3};"
        : "+f"(c[0]), "+f"(c[1]), "+f"(c[2]), "+f"(c[3])
        : "r"(a[0]), "r"(a[1]), "r"(a[2]), "r"(a[3]), "r"(b[0]), "r"(b[1]));
}

// ---------------- weight pre-rounding ----------------------------------------
__global__ void round_copy_kernel(const float* __restrict__ in, float* __restrict__ out, int n4)
{
    int i = blockIdx.x * blockDim.x + threadIdx.x;
    if (i >= n4) return;
    float4 v = *(const float4*)(in + i * 4);
    float4 o;
    o.x = to_tf32(v.x); o.y = to_tf32(v.y); o.z = to_tf32(v.z); o.w = to_tf32(v.w);
    *(float4*)(out + i * 4) = o;
}

// -------- fused flatten+transpose; emits full & rounded activations ----------
__global__ void flatten2_kernel(const float* __restrict__ in_src, const float* __restrict__ in_pos,
                                float* __restrict__ out_src, float* __restrict__ out_srcr,
                                float* __restrict__ out_pos, float* __restrict__ out_qr,
                                const float* __restrict__ lvl_emb, int S, int base)
{
    __shared__ float tS[32][33];
    __shared__ float tP[32][33];
    const int b  = blockIdx.z;
    const int s0 = blockIdx.x * 32;
    const int c0 = blockIdx.y * 32;
    const int tx = threadIdx.x, ty = threadIdx.y; // 32 x 8

    #pragma unroll
    for (int i = 0; i < 32; i += 8) {
        int c = c0 + ty + i, s = s0 + tx;
        float vs = 0.f, vp = 0.f;
        if (s < S) {
            vs = in_src[((size_t)b * DM_ + c) * S + s];
            vp = in_pos[((size_t)b * DM_ + c) * S + s];
        }
        tS[ty + i][tx] = vs;
        tP[ty + i][tx] = vp;
    }
    __syncthreads();
    float emb = lvl_emb[c0 + tx];
    #pragma unroll
    for (int i = 0; i < 32; i += 8) {
        int s = s0 + ty + i, c = c0 + tx;
        if (s < S) {
            size_t o = ((size_t)b * LEN_ + base + s) * DM_ + c;
            float sv = tS[tx][ty + i];
            float pv = tP[tx][ty + i] + emb;
            out_src [o] = sv;
            out_srcr[o] = to_tf32(sv);
            out_pos [o] = pv;
            out_qr  [o] = to_tf32(sv + pv);
        }
    }
}

// ---------------- TF32 GEMM: cp.async 3-stage pipeline, BK=32 ----------------
// Inputs (A and W) are PRE-ROUNDED tf32 values stored as fp32.
__global__ __launch_bounds__(256, 2) void tgemm_kernel(
    const float* __restrict__ A, const float* __restrict__ W,
    const float* __restrict__ bias, float* __restrict__ C,
    int Mrows, int N, int K, int relu, int round_out)
{
    extern __shared__ float sm[];
    const int bm = blockIdx.y * 128;
    const int bn = blockIdx.x * 128;
    const int tid  = threadIdx.x;
    const int wid  = tid >> 5;
    const int lane = tid & 31;
    const int g    = lane >> 2;
    const int t4   = lane & 3;
    const int wm   = (wid & 1) * 64;
    const int wn   = (wid >> 1) * 32;

    float acc[4][4][4];
    #pragma unroll
    for (int i = 0; i < 4; i++)
        #pragma unroll
        for (int j = 0; j < 4; j++)
            #pragma unroll
            for (int r = 0; r < 4; r++) acc[i][j][r] = 0.f;

    auto issue = [&](int s) {
        float* As = sm + (s % NSTAGE) * STG_SZ;
        float* Bs = As + A_SZ;
        int k0 = s * BK;
        #pragma unroll
        for (int t = 0; t < 4; t++) {
            int c   = tid + t * 256;          // 1024 chunks
            int row = c >> 3;                 // 0..127
            int kc  = (c & 7) * 4;            // 0..28
            const float* gp = A + (size_t)(bm + row) * K + k0 + kc;
            uint32_t sp = (uint32_t)__cvta_generic_to_shared(As + row * A_STRIDE + kc);
            int sz = (bm + row < Mrows) ? 16 : 0;
            asm volatile("cp.async.cg.shared.global [%0], [%1], 16, %2;\n"
                         :: "r"(sp), "l"(gp), "r"(sz));
        }
        #pragma unroll
        for (int t = 0; t < 4; t++) {
            int c  = tid + t * 256;
            int kr = c >> 5;                  // 0..31
            int nc = (c & 31) * 4;            // 0..124
            const float* gp = W + (size_t)(k0 + kr) * N + bn + nc;
            uint32_t sp = (uint32_t)__cvta_generic_to_shared(Bs + kr * B_STRIDE + nc);
            asm volatile("cp.async.cg.shared.global [%0], [%1], 16;\n"
                         :: "r"(sp), "l"(gp));
        }
        asm volatile("cp.async.commit_group;\n");
    };

    auto compute = [&](int s) {
        const float* As = sm + (s % NSTAGE) * STG_SZ;
        const float* Bs = As + A_SZ;
        #pragma unroll
        for (int kk = 0; kk < BK; kk += 8) {
            uint32_t af[4][4];
            #pragma unroll
            for (int mf = 0; mf < 4; mf++) {
                int mb = wm + mf * 16 + g;
                af[mf][0] = __float_as_uint(As[mb * A_STRIDE       + kk + t4    ]);
                af[mf][1] = __float_as_uint(As[(mb + 8) * A_STRIDE + kk + t4    ]);
                af[mf][2] = __float_as_uint(As[mb * A_STRIDE       + kk + t4 + 4]);
                af[mf][3] = __float_as_uint(As[(mb + 8) * A_STRIDE + kk + t4 + 4]);
            }
            uint32_t bf[4][2];
            #pragma unroll
            for (int nf = 0; nf < 4; nf++) {
                int nb = wn + nf * 8 + g;
                bf[nf][0] = __float_as_uint(Bs[(kk + t4    ) * B_STRIDE + nb]);
                bf[nf][1] = __float_as_uint(Bs[(kk + t4 + 4) * B_STRIDE + nb]);
            }
            #pragma unroll
            for (int mf = 0; mf < 4; mf++)
                #pragma unroll
                for (int nf = 0; nf < 4; nf++)
                    mma_tf32(acc[mf][nf], af[mf], bf[nf]);
        }
    };

    const int nslab = K / BK;
    issue(0);
    issue(1);
    for (int s = 0; s < nslab; s++) {
        if (s + 1 < nslab) asm volatile("cp.async.wait_group 1;\n" ::: "memory");
        else               asm volatile("cp.async.wait_group 0;\n" ::: "memory");
        __syncthreads();
        if (s + 2 < nslab) issue(s + 2);
        compute(s);
    }

    // ---- epilogue ----
    #pragma unroll
    for (int mf = 0; mf < 4; mf++) {
        int row0 = bm + wm + mf * 16 + g;
        int row1 = row0 + 8;
        #pragma unroll
        for (int nf = 0; nf < 4; nf++) {
            int col = bn + wn + nf * 8 + 2 * t4;
            float b0 = bias[col], b1 = bias[col + 1];
            float v0 = acc[mf][nf][0] + b0;
            float v1 = acc[mf][nf][1] + b1;
            float v2 = acc[mf][nf][2] + b0;
            float v3 = acc[mf][nf][3] + b1;
            if (relu) {
                v0 = fmaxf(v0, 0.f); v1 = fmaxf(v1, 0.f);
                v2 = fmaxf(v2, 0.f); v3 = fmaxf(v3, 0.f);
            }
            if (round_out) {
                v0 = to_tf32(v0); v1 = to_tf32(v1);
                v2 = to_tf32(v2); v3 = to_tf32(v3);
            }
            if (row0 < Mrows) *(float2*)(C + (size_t)row0 * N + col) = make_float2(v0, v1);
            if (row1 < Mrows) *(float2*)(C + (size_t)row1 * N + col) = make_float2(v2, v3);
        }
    }
}

// ---------------- softmax over 16 (per b,n,m) --------------------------------
__global__ void softmax_kernel(float* __restrict__ attn, int total)
{
    int i = blockIdx.x * blockDim.x + threadIdx.x;
    if (i >= total) return;
    float* p = attn + (size_t)i * 16;
    float v[16];
    #pragma unroll
    for (int t = 0; t < 4; t++) {
        float4 f = *(float4*)(p + t * 4);
        v[t*4+0] = f.x; v[t*4+1] = f.y; v[t*4+2] = f.z; v[t*4+3] = f.w;
    }
    float mx = v[0];
    #pragma unroll
    for (int t = 1; t < 16; t++) mx = fmaxf(mx, v[t]);
    float s = 0.f;
    #pragma unroll
    for (int t = 0; t < 16; t++) { v[t] = expf(v[t] - mx); s += v[t]; }
    float inv = 1.f / s;
    #pragma unroll
    for (int t = 0; t < 4; t++) {
        float4 f = make_float4(v[t*4+0]*inv, v[t*4+1]*inv, v[t*4+2]*inv, v[t*4+3]*inv);
        *(float4*)(p + t * 4) = f;
    }
}

// ---------------- deformable trilinear sampling (rounded output) -------------
__global__ __launch_bounds__(256) void sample_kernel(
    const float* __restrict__ value, const float* __restrict__ off,
    const float* __restrict__ attn, float* __restrict__ agg)
{
    const int bn = blockIdx.x;
    const int b  = bn / LEN_;
    const int n  = bn - b * LEN_;
    const int tid = threadIdx.x;
    const int m  = tid >> 5, dh = tid & 31;

    float rc0, rc1, rc2;
    {
        int s, z, r, y, x;
        if (n < 16384)      { s = n;         z = s >> 10; r = s & 1023; y = r >> 5; x = r & 31;
            rc0 = (z + .5f) * (1.f/16.f); rc1 = (y + .5f) * (1.f/32.f); rc2 = (x + .5f) * (1.f/32.f); }
        else if (n < 18432) { s = n - 16384; z = s >> 8;  r = s & 255;  y = r >> 4; x = r & 15;
            rc0 = (z + .5f) * (1.f/8.f);  rc1 = (y + .5f) * (1.f/16.f); rc2 = (x + .5f) * (1.f/16.f); }
        else if (n < 18688) { s = n - 18432; z = s >> 6;  r = s & 63;   y = r >> 3; x = r & 7;
            rc0 = (z + .5f) * (1.f/4.f);  rc1 = (y + .5f) * (1.f/8.f);  rc2 = (x + .5f) * (1.f/8.f); }
        else                { s = n - 18688; z = s >> 4;  r = s & 15;   y = r >> 2; x = r & 3;
            rc0 = (z + .5f) * .5f;        rc1 = (y + .5f) * .25f;       rc2 = (x + .5f) * .25f; }
    }

    const float* offp = off  + ((size_t)bn * 8 + m) * 48;
    const float* attp = attn + ((size_t)bn * 8 + m) * 16;

    const int LD[4] = {16, 8, 4, 2};
    const int LH[4] = {32, 16, 8, 4};
    const int LW[4] = {32, 16, 8, 4};
    const int LB[4] = {0, 16384, 18432, 18688};

    float acc0 = 0.f, acc1 = 0.f;
    #pragma unroll
    for (int lvl = 0; lvl < 4; lvl++) {
        const int D = LD[lvl], H = LH[lvl], Wd = LW[lvl];
        const float* vptr = value + ((size_t)b * LEN_ + LB[lvl]) * DM_ + m * 32 + dh;
        #pragma unroll
        for (int p = 0; p < 4; p++) {
            float o0 = __ldg(offp + lvl * 12 + p * 3 + 0);
            float o1 = __ldg(offp + lvl * 12 + p * 3 + 1);
            float o2 = __ldg(offp + lvl * 12 + p * 3 + 2);
            float a  = __ldg(attp + lvl * 4 + p);
            float x = fmaf(rc0, (float)Wd, o0) - 0.5f;
            float y = fmaf(rc1, (float)H,  o1) - 0.5f;
            float z = fmaf(rc2, (float)D,  o2) - 0.5f;
            float xf = floorf(x), yf = floorf(y), zf = floorf(z);
            float fx = x - xf, fy = y - yf, fz = z - zf;
            int x0 = (int)xf, y0 = (int)yf, z0 = (int)zf;
            float wx0 = (1.f - fx) * a, wx1 = fx * a;
            float wy0 = 1.f - fy,       wy1 = fy;
            float wz0 = 1.f - fz,       wz1 = fz;
            #pragma unroll
            for (int dz = 0; dz < 2; dz++) {
                int zi = z0 + dz;
                if ((unsigned)zi >= (unsigned)D) continue;
                float wz_ = dz ? wz1 : wz0;
                #pragma unroll
                for (int dy = 0; dy < 2; dy++) {
                    int yi = y0 + dy;
                    if ((unsigned)yi >= (unsigned)H) continue;
                    float wzy = wz_ * (dy ? wy1 : wy0);
                    #pragma unroll
                    for (int dx = 0; dx < 2; dx++) {
                        int xi = x0 + dx;
                        if ((unsigned)xi >= (unsigned)Wd) continue;
                        float w = wzy * (dx ? wx1 : wx0);
                        int idx = (zi * H + yi) * Wd + xi;
                        float vv = __ldg(vptr + (size_t)idx * DM_);
                        if (dz) acc1 = fmaf(w, vv, acc1);
                        else    acc0 = fmaf(w, vv, acc0);
                    }
                }
            }
        }
    }
    agg[(size_t)bn * DM_ + tid] = to_tf32(acc0 + acc1);   // feeds out-proj A-side
}

// -------- fused residual + LayerNorm; optional rounded / q outputs -----------
__global__ void addln_kernel(const float* __restrict__ X, const float* __restrict__ R,
                             const float* __restrict__ g, const float* __restrict__ bta,
                             float* __restrict__ out, float* __restrict__ out_r,
                             const float* __restrict__ pos, float* __restrict__ q_r,
                             int rows)
{
    int w    = (blockIdx.x * blockDim.x + threadIdx.x) >> 5;
    int lane = threadIdx.x & 31;
    if (w >= rows) return;
    const float* xp = X + (size_t)w * DM_;
    const float* rp = R + (size_t)w * DM_;
    int c0 = lane * 4, c1 = 128 + lane * 4;

    float4 x0 = *(const float4*)(xp + c0);
    float4 x1 = *(const float4*)(xp + c1);
    float4 r0 = *(const float4*)(rp + c0);
    float4 r1 = *(const float4*)(rp + c1);
    float v[8];
    v[0] = x0.x + r0.x; v[1] = x0.y + r0.y; v[2] = x0.z + r0.z; v[3] = x0.w + r0.w;
    v[4] = x1.x + r1.x; v[5] = x1.y + r1.y; v[6] = x1.z + r1.z; v[7] = x1.w + r1.w;

    float s = 0.f;
    #pragma unroll
    for (int i = 0; i < 8; i++) s += v[i];
    #pragma unroll
    for (int o = 16; o > 0; o >>= 1) s += __shfl_xor_sync(0xFFFFFFFFu, s, o);
    float mu = s * (1.f / 256.f);

    float q = 0.f;
    #pragma unroll
    for (int i = 0; i < 8; i++) { float d = v[i] - mu; q += d * d; }
    #pragma unroll
    for (int o = 16; o > 0; o >>= 1) q += __shfl_xor_sync(0xFFFFFFFFu, q, o);
    float rs = rsqrtf(q * (1.f / 256.f) + 1e-5f);

    float o0[4], o1[4];
    #pragma unroll
    for (int i = 0; i < 4; i++) {
        o0[i] = (v[i]     - mu) * rs * g[c0 + i] + bta[c0 + i];
        o1[i] = (v[4 + i] - mu) * rs * g[c1 + i] + bta[c1 + i];
    }
    *(float4*)(out + (size_t)w * DM_ + c0) = *(float4*)&o0[0];
    *(float4*)(out + (size_t)w * DM_ + c1) = *(float4*)&o1[0];

    if (out_r) {
        float r0o[4], r1o[4];
        #pragma unroll
        for (int i = 0; i < 4; i++) { r0o[i] = to_tf32(o0[i]); r1o[i] = to_tf32(o1[i]); }
        *(float4*)(out_r + (size_t)w * DM_ + c0) = *(float4*)&r0o[0];
        *(float4*)(out_r + (size_t)w * DM_ + c1) = *(float4*)&r1o[0];
    }
    if (q_r) {
        float4 p0 = *(const float4*)(pos + (size_t)w * DM_ + c0);
        float4 p1 = *(const float4*)(pos + (size_t)w * DM_ + c1);
        float q0[4], q1[4];
        q0[0] = to_tf32(o0[0] + p0.x); q0[1] = to_tf32(o0[1] + p0.y);
        q0[2] = to_tf32(o0[2] + p0.z); q0[3] = to_tf32(o0[3] + p0.w);
        q1[0] = to_tf32(o1[0] + p1.x); q1[1] = to_tf32(o1[1] + p1.y);
        q1[2] = to_tf32(o1[2] + p1.z); q1[3] = to_tf32(o1[3] + p1.w);
        *(float4*)(q_r + (size_t)w * DM_ + c0) = *(float4*)&q0[0];
        *(float4*)(q_r + (size_t)w * DM_ + c1) = *(float4*)&q1[0];
    }
}

// ---------------- host orchestration -----------------------------------------
extern "C" void kernel_launch(void* const* d_in, const int* in_sizes, int n_in,
                              void* d_out, int out_size)
{
    const float* srcs[4] = {(const float*)d_in[0], (const float*)d_in[2],
                            (const float*)d_in[4], (const float*)d_in[6]};
    const float* poss[4] = {(const float*)d_in[1], (const float*)d_in[3],
                            (const float*)d_in[5], (const float*)d_in[7]};
    const float* lvl_emb = (const float*)d_in[8];
    const float* W_off  = (const float*)d_in[9],  *b_off  = (const float*)d_in[10];
    const float* W_attn = (const float*)d_in[11], *b_attn = (const float*)d_in[12];
    const float* W_val  = (const float*)d_in[13], *b_val  = (const float*)d_in[14];
    const float* W_out  = (const float*)d_in[15], *b_out  = (const float*)d_in[16];
    const float* ln1_g  = (const float*)d_in[17], *ln1_b  = (const float*)d_in[18];
    const float* W_ff1  = (const float*)d_in[19], *b_ff1  = (const float*)d_in[20];
    const float* W_ff2  = (const float*)d_in[21], *b_ff2  = (const float*)d_in[22];
    const float* ln2_g  = (const float*)d_in[23], *ln2_b  = (const float*)d_in[24];

    float *src_b, *srcr_b, *qr_b, *pos_b, *val_b, *agg_b, *off_b, *attn_b, *ff_b, *w_b;
    cudaGetSymbolAddress((void**)&src_b,  g_src);
    cudaGetSymbolAddress((void**)&srcr_b, g_srcr);
    cudaGetSymbolAddress((void**)&qr_b,   g_qr);
    cudaGetSymbolAddress((void**)&pos_b,  g_pos);
    cudaGetSymbolAddress((void**)&val_b,  g_val);
    cudaGetSymbolAddress((void**)&agg_b,  g_agg);
    cudaGetSymbolAddress((void**)&off_b,  g_off);
    cudaGetSymbolAddress((void**)&attn_b, g_attn);
    cudaGetSymbolAddress((void**)&ff_b,   g_ff);
    cudaGetSymbolAddress((void**)&w_b,    g_w);

    cudaFuncSetAttribute(tgemm_kernel, cudaFuncAttributeMaxDynamicSharedMemorySize, SMEM_BYTES);

    // rounded-weight scratch layout (both layers contiguous, matching inputs)
    const int SZ_VAL = 2 * 256 * 256;    // 131072
    const int SZ_OFF = 2 * 256 * 384;    // 196608
    const int SZ_ATT = 2 * 256 * 128;    // 65536
    const int SZ_OUT = 2 * 256 * 256;    // 131072
    const int SZ_FF1 = 2 * 256 * 1024;   // 524288
    float* wr_val = w_b;
    float* wr_off = wr_val + SZ_VAL;
    float* wr_att = wr_off + SZ_OFF;
    float* wr_out = wr_att + SZ_ATT;
    float* wr_ff1 = wr_out + SZ_OUT;
    float* wr_ff2 = wr_ff1 + SZ_FF1;

    round_copy_kernel<<<(SZ_VAL/4 + 255)/256, 256>>>(W_val,  wr_val, SZ_VAL/4);
    round_copy_kernel<<<(SZ_OFF/4 + 255)/256, 256>>>(W_off,  wr_off, SZ_OFF/4);
    round_copy_kernel<<<(SZ_ATT/4 + 255)/256, 256>>>(W_attn, wr_att, SZ_ATT/4);
    round_copy_kernel<<<(SZ_OUT/4 + 255)/256, 256>>>(W_out,  wr_out, SZ_OUT/4);
    round_copy_kernel<<<(SZ_FF1/4 + 255)/256, 256>>>(W_ff1,  wr_ff1, SZ_FF1/4);
    round_copy_kernel<<<(SZ_FF1/4 + 255)/256, 256>>>(W_ff2,  wr_ff2, SZ_FF1/4);

    const int sizes[4] = {16384, 2048, 256, 32};
    const int bases[4] = {0, 16384, 18432, 18688};
    for (int lv = 0; lv < 4; lv++) {
        dim3 gr((sizes[lv] + 31) / 32, DM_ / 32, BATCH);
        dim3 bl(32, 8);
        flatten2_kernel<<<gr, bl>>>(srcs[lv], poss[lv], src_b, srcr_b, pos_b, qr_b,
                                    lvl_emb + lv * DM_, sizes[lv], bases[lv]);
    }

    const int MT = (ROWS_ + 127) / 128;  // 293
    dim3 thr(256);
    for (int l = 0; l < 2; l++) {
        tgemm_kernel<<<dim3(2, MT), thr, SMEM_BYTES>>>(srcr_b,
            wr_val + (size_t)l * 256 * 256,  b_val + l * DM_,  val_b,  ROWS_, 256,  256, 0, 0);
        tgemm_kernel<<<dim3(3, MT), thr, SMEM_BYTES>>>(qr_b,
            wr_off + (size_t)l * 256 * NOFF, b_off + l * NOFF, off_b,  ROWS_, NOFF, 256, 0, 0);
        tgemm_kernel<<<dim3(1, MT), thr, SMEM_BYTES>>>(qr_b,
            wr_att + (size_t)l * 256 * NATT, b_attn + l * NATT, attn_b, ROWS_, NATT, 256, 0, 0);
        softmax_kernel<<<(ROWS_ * 8 + 255) / 256, 256>>>(attn_b, ROWS_ * 8);
        sample_kernel<<<ROWS_, 256>>>(val_b, off_b, attn_b, agg_b);
        tgemm_kernel<<<dim3(2, MT), thr, SMEM_BYTES>>>(agg_b,
            wr_out + (size_t)l * 256 * 256, b_out + l * DM_, val_b, ROWS_, 256, 256, 0, 0);
        addln_kernel<<<(ROWS_ + 7) / 8, 256>>>(src_b, val_b,
            ln1_g + l * DM_, ln1_b + l * DM_, src_b, srcr_b, nullptr, nullptr, ROWS_);
        tgemm_kernel<<<dim3(8, MT), thr, SMEM_BYTES>>>(srcr_b,
            wr_ff1 + (size_t)l * 256 * DFF_, b_ff1 + l * DFF_, ff_b, ROWS_, DFF_, 256, 1, 1);
        tgemm_kernel<<<dim3(2, MT), thr, SMEM_BYTES>>>(ff_b,
            wr_ff2 + (size_t)l * DFF_ * 256, b_ff2 + l * DM_, val_b, ROWS_, 256, DFF_, 0, 0);
        if (l == 1) {
            addln_kernel<<<(ROWS_ + 7) / 8, 256>>>(src_b, val_b,
                ln2_g + l * DM_, ln2_b + l * DM_, (float*)d_out, nullptr, nullptr, nullptr, ROWS_);
        } else {
            addln_kernel<<<(ROWS_ + 7) / 8, 256>>>(src_b, val_b,
                ln2_g + l * DM_, ln2_b + l * DM_, src_b, srcr_b, pos_b, qr_b, ROWS_);
        }
    }
}